// round 14
// baseline (speedup 1.0000x reference)
#include <cuda_runtime.h>
#include <math.h>

// ============================================================================
// QuanvolutionFilter via fixed-unitary reduction + monomial (double-angle)
// basis. f32x2 lanes = output pairs (k0,k1)/(k2,k3): one LDC.128 per slot
// carries all 4 outputs' coefficients; 2 patches/thread share each load.
// 6 blocks/SM (42 regs) for latency hiding.
//
//   out_k(patch) = sum_{u,v} D_k[u][v] * m01[u] * m23[v]
//   m01 = {1,C0,S0}x{1,C1,S1}, m23 = {1,C2,S2}x{1,C3,S3}
//   unit entries (u=0 / v=0 / (0,0)) handled without multiplies.
// ============================================================================

#define PACK_F32X2(out, lo, hi) \
    asm("mov.b64 %0, {%1, %2};" : "=l"(out) : "f"(lo), "f"(hi))
#define UNPACK_F32X2(lo, hi, in) \
    asm("mov.b64 {%0, %1}, %2;" : "=f"(lo), "=f"(hi) : "l"(in))
#define FMA_F32X2(d, a, b, c) \
    asm("fma.rn.f32x2 %0, %1, %2, %3;" : "=l"(d) : "l"(a), "l"(b), "l"(c))

// coefficient slot (u*9+v): one float4 = (D0,D1,D2,D3)
__device__ __align__(16) float g_D[81 * 4];
__constant__ ulonglong2 cD[81];

// E[f][f'][alpha]: coefficient of monomial {1, cos a, sin a}[alpha] in the
// half-angle product p(f,f'), f,f' in {0=cos(a/2),1=sin(a/2)}.
__device__ __forceinline__ float Ecoef(int f, int fp, int al) {
    if (al == 2) return (f != fp) ? 0.5f : 0.0f;   // cs -> sin(a)/2
    if (f != fp) return 0.0f;
    if (al == 0) return 0.5f;                       // cc,ss -> 1/2
    return f ? -0.5f : 0.5f;                        // cc -> +cos/2, ss -> -cos/2
}

__global__ void qsetup(const float* __restrict__ params,   // (3,4,3)
                       const float* __restrict__ W,        // (4,4)
                       const float* __restrict__ bvec)     // (4,)
{
    __shared__ float Ur[2][16][17];
    __shared__ float Ui[2][16][17];
    __shared__ float sG[12][8];
    __shared__ float sA[4][16][16];
    __shared__ float sS[4][4][4][9];
    __shared__ float sDt[4][9][9];

    const int t = threadIdx.x;
    const int n = t >> 4, c = t & 15;

    // --- phase A: 12 Rot gate matrices (fast trig) --------------------------
    if (t < 12) {
        float phi = params[t * 3 + 0];
        float th  = params[t * 3 + 1];
        float om  = params[t * 3 + 2];
        float ct, st, ca, sa, cb, sb;
        __sincosf(0.5f * th,         &st, &ct);
        __sincosf(0.5f * (phi + om), &sa, &ca);
        __sincosf(0.5f * (phi - om), &sb, &cb);
        sG[t][0] =  ca * ct;  sG[t][1] = -sa * ct;   // m00
        sG[t][2] = -cb * st;  sG[t][3] = -sb * st;   // m01
        sG[t][4] =  cb * st;  sG[t][5] = -sb * st;   // m10
        sG[t][6] =  ca * ct;  sG[t][7] =  sa * ct;   // m11
    }
    Ur[0][n][c] = (n == c) ? 1.0f : 0.0f;
    Ui[0][n][c] = 0.0f;
    __syncthreads();

    // --- phase B: gates + perms, double-buffered (1 barrier per step) ------
    int cur = 0;
    #pragma unroll
    for (int l = 0; l < 3; ++l) {
        #pragma unroll
        for (int w = 0; w < 4; ++w) {
            const int mask = 8 >> w;                 // wire 0 = MSB of row idx
            const float* g = sG[l * 4 + w];
            float xr = Ur[cur][n][c],        xi = Ui[cur][n][c];
            float yr = Ur[cur][n ^ mask][c], yi = Ui[cur][n ^ mask][c];
            float nr, ni;
            if (!(n & mask)) {
                nr = g[0]*xr - g[1]*xi + g[2]*yr - g[3]*yi;
                ni = g[0]*xi + g[1]*xr + g[2]*yi + g[3]*yr;
            } else {
                nr = g[4]*yr - g[5]*yi + g[6]*xr - g[7]*xi;
                ni = g[4]*yi + g[5]*yr + g[6]*xi + g[7]*xr;
            }
            Ur[cur ^ 1][n][c] = nr; Ui[cur ^ 1][n][c] = ni;
            __syncthreads();
            cur ^= 1;
        }
        // composed permutation of the layer's 4 sequential CNOTs
        const int r = (l % 3) + 1;
        int m = n;
        #pragma unroll
        for (int w = 3; w >= 0; --w) {
            const int cm = 8 >> w, tm = 8 >> ((w + r) & 3);
            if (m & cm) m ^= tm;
        }
        Ur[cur ^ 1][n][c] = Ur[cur][m][c];
        Ui[cur ^ 1][n][c] = Ui[cur][m][c];
        __syncthreads();
        cur ^= 1;
    }

    // --- phase C: A_k[i][j] = sum_w W[k][w] * Re(U^H Z_w U)[i][j] ----------
    {
        const int i = n, j = c;
        float M[4] = {0.f, 0.f, 0.f, 0.f};
        #pragma unroll
        for (int nn = 0; nn < 16; ++nn) {
            float v = Ur[cur][nn][i] * Ur[cur][nn][j]
                    + Ui[cur][nn][i] * Ui[cur][nn][j];
            #pragma unroll
            for (int w = 0; w < 4; ++w)
                M[w] += (nn & (8 >> w)) ? -v : v;
        }
        #pragma unroll
        for (int k = 0; k < 4; ++k) {
            float acc = 0.0f;
            #pragma unroll
            for (int w = 0; w < 4; ++w) acc += W[k * 4 + w] * M[w];
            sA[k][i][j] = acc;
        }
    }
    __syncthreads();

    // --- phase D stage 1: contract wires 2,3 ------------------------------
    for (int idx = t; idx < 576; idx += 256) {
        int k   = idx / 144;
        int rem = idx - k * 144;
        int i01 = rem / 36;
        int r2  = rem - i01 * 36;
        int j01 = r2 / 9;
        int v   = r2 - j01 * 9;
        int a2 = v / 3, a3 = v - a2 * 3;
        float acc = 0.0f;
        #pragma unroll
        for (int i23 = 0; i23 < 4; ++i23)
            #pragma unroll
            for (int j23 = 0; j23 < 4; ++j23) {
                float e = Ecoef(i23 >> 1, j23 >> 1, a2) * Ecoef(i23 & 1, j23 & 1, a3);
                acc += e * sA[k][i01 * 4 + i23][j01 * 4 + j23];
            }
        sS[k][i01][j01][v] = acc;
    }
    __syncthreads();

    // --- phase D stage 2: contract wires 0,1; fold bias --------------------
    for (int idx = t; idx < 324; idx += 256) {
        int k  = idx / 81;
        int uv = idx - k * 81;
        int u  = uv / 9;
        int v  = uv - u * 9;
        int a0 = u / 3, a1 = u - a0 * 3;
        float acc = 0.0f;
        #pragma unroll
        for (int i01 = 0; i01 < 4; ++i01)
            #pragma unroll
            for (int j01 = 0; j01 < 4; ++j01) {
                float e = Ecoef(i01 >> 1, j01 >> 1, a0) * Ecoef(i01 & 1, j01 & 1, a1);
                acc += e * sS[k][i01][j01][v];
            }
        if (u == 0 && v == 0) acc += bvec[k];
        sDt[k][u][v] = acc;
    }
    __syncthreads();

    // --- pack: slot t=(u*9+v) -> float4 (D0,D1,D2,D3) ----------------------
    if (t < 81) {
        int u = t / 9, v = t - u * 9;
        reinterpret_cast<float4*>(g_D)[t] =
            make_float4(sDt[0][u][v], sDt[1][u][v], sDt[2][u][v], sDt[3][u][v]);
    }
}

__device__ __forceinline__ void patch_angles(const float* __restrict__ x, int gid,
                                             float* C, float* S)
{
    int b  = gid / 196;
    int p  = gid - b * 196;
    int pr = p / 14;
    int pc = p - pr * 14;
    const float* img = x + b * 784 + pr * 56 + pc * 2;
    float2 r0 = *reinterpret_cast<const float2*>(img);
    float2 r1 = *reinterpret_cast<const float2*>(img + 28);
    __sincosf(r0.x, &S[0], &C[0]);
    __sincosf(r0.y, &S[1], &C[1]);
    __sincosf(r1.x, &S[2], &C[2]);
    __sincosf(r1.y, &S[3], &C[3]);
}

__global__ void __launch_bounds__(256, 6) qmain(const float* __restrict__ x,
                                                float* __restrict__ out,
                                                int half, int total)
{
    int g0 = blockIdx.x * blockDim.x + threadIdx.x;
    if (g0 >= half) return;
    int g1 = g0 + half;
    bool has1 = (g1 < total);

    // hoist acc init (LDC) to overlap with sincos latency
    unsigned long long a01A, a23A, a01B, a23B;
    {
        ulonglong2 w = cD[0];
        a01A = w.x; a23A = w.y;
        a01B = w.x; a23B = w.y;
    }

    float Ca[4], Sa[4], Cb[4], Sb[4];           // [wire], patch A / patch B
    patch_angles(x, g0, Ca, Sa);
    patch_angles(x, has1 ? g1 : g0, Cb, Sb);

    // m23[v], v=1..8 : {C3, S3, C2, C2C3, C2S3, S2, S2C3, S2S3} (scalar)
    float m3a[8] = { Ca[3], Sa[3], Ca[2], Ca[2]*Ca[3], Ca[2]*Sa[3],
                     Sa[2], Sa[2]*Ca[3], Sa[2]*Sa[3] };
    float m3b[8] = { Cb[3], Sb[3], Cb[2], Cb[2]*Cb[3], Cb[2]*Sb[3],
                     Sb[2], Sb[2]*Cb[3], Sb[2]*Sb[3] };

    #pragma unroll
    for (int u = 0; u < 9; ++u) {
        // scalar m01[u] per patch
        float mA = 1.0f, mB = 1.0f;
        if      (u == 1) { mA = Ca[1];        mB = Cb[1]; }
        else if (u == 2) { mA = Sa[1];        mB = Sb[1]; }
        else if (u == 3) { mA = Ca[0];        mB = Cb[0]; }
        else if (u == 4) { mA = Ca[0]*Ca[1];  mB = Cb[0]*Cb[1]; }
        else if (u == 5) { mA = Ca[0]*Sa[1];  mB = Cb[0]*Sb[1]; }
        else if (u == 6) { mA = Sa[0];        mB = Sb[0]; }
        else if (u == 7) { mA = Sa[0]*Ca[1];  mB = Sb[0]*Cb[1]; }
        else if (u == 8) { mA = Sa[0]*Sa[1];  mB = Sb[0]*Sb[1]; }

        #pragma unroll
        for (int v = 0; v < 9; ++v) {
            if (u == 0 && v == 0) continue;     // folded into acc init
            ulonglong2 w = cD[u * 9 + v];       // (D0,D1),(D2,D3)

            float tA, tB;
            if (u == 0)      { tA = m3a[v - 1];      tB = m3b[v - 1]; }
            else if (v == 0) { tA = mA;              tB = mB; }
            else             { tA = mA * m3a[v - 1]; tB = mB * m3b[v - 1]; }

            unsigned long long tA2, tB2;
            PACK_F32X2(tA2, tA, tA);
            PACK_F32X2(tB2, tB, tB);

            FMA_F32X2(a01A, w.x, tA2, a01A);
            FMA_F32X2(a23A, w.y, tA2, a23A);
            FMA_F32X2(a01B, w.x, tB2, a01B);
            FMA_F32X2(a23B, w.y, tB2, a23B);
        }
    }

    float o0, o1, o2, o3;
    UNPACK_F32X2(o0, o1, a01A);
    UNPACK_F32X2(o2, o3, a23A);
    reinterpret_cast<float4*>(out)[g0] = make_float4(o0, o1, o2, o3);

    UNPACK_F32X2(o0, o1, a01B);
    UNPACK_F32X2(o2, o3, a23B);
    if (has1)
        reinterpret_cast<float4*>(out)[g1] = make_float4(o0, o1, o2, o3);
}

extern "C" void kernel_launch(void* const* d_in, const int* in_sizes, int n_in,
                              void* d_out, int out_size)
{
    const float* x      = (const float*)d_in[0];   // (B,1,28,28)
    const float* params = (const float*)d_in[1];   // (3,4,3)
    const float* W      = (const float*)d_in[2];   // (4,4)
    const float* bvec   = (const float*)d_in[3];   // (4,)
    float* out = (float*)d_out;                    // (B, 784)

    int total = in_sizes[0] / 4;                   // B*196 patches
    int half  = (total + 1) / 2;

    qsetup<<<1, 256>>>(params, W, bvec);

    // stage device-computed coefficients into constant memory (D2D, capturable)
    void* gptr = nullptr;
    cudaGetSymbolAddress(&gptr, g_D);
    cudaMemcpyToSymbolAsync(cD, gptr, sizeof(float) * 81 * 4, 0,
                            cudaMemcpyDeviceToDevice, 0);

    qmain<<<(half + 255) / 256, 256>>>(x, out, half, total);
}

// round 15
// speedup vs baseline: 1.1115x; 1.1115x over previous
#include <cuda_runtime.h>
#include <math.h>

// ============================================================================
// QuanvolutionFilter via fixed-unitary reduction + monomial (double-angle)
// basis. f32x2 lanes = output pairs (k0,k1)/(k2,k3); one LDC.128 per slot
// carries all 4 outputs' coefficients, shared by 2 patches/thread.
// Horner factorization over the m23 tensor structure removes all per-slot
// scalar muls/packs:
//   out_k = sum_u m01[u] * q_u,
//   q_u   = (w0 + C3 w1 + S3 w2) + C2 (w3 + C3 w4 + S3 w5)
//                                + S2 (w6 + C3 w7 + S3 w8)
// ============================================================================

#define PACK_F32X2(out, lo, hi) \
    asm("mov.b64 %0, {%1, %2};" : "=l"(out) : "f"(lo), "f"(hi))
#define UNPACK_F32X2(lo, hi, in) \
    asm("mov.b64 {%0, %1}, %2;" : "=f"(lo), "=f"(hi) : "l"(in))
#define FMA_F32X2(d, a, b, c) \
    asm("fma.rn.f32x2 %0, %1, %2, %3;" : "=l"(d) : "l"(a), "l"(b), "l"(c))

// q = w0 + C3p*w1 + S3p*w2  (packed halves)
#define GROUP_EVAL(res, w0h, w1h, w2h, C3p, S3p) \
    { unsigned long long _t;                     \
      FMA_F32X2(_t, C3p, w1h, w0h);              \
      FMA_F32X2(res, S3p, w2h, _t); }

// coefficient slot (u*9+v): one float4 = (D0,D1,D2,D3)
__device__ __align__(16) float g_D[81 * 4];
__constant__ ulonglong2 cD[81];

// E[f][f'][alpha]: coefficient of monomial {1, cos a, sin a}[alpha] in the
// half-angle product p(f,f'), f,f' in {0=cos(a/2),1=sin(a/2)}.
__device__ __forceinline__ float Ecoef(int f, int fp, int al) {
    if (al == 2) return (f != fp) ? 0.5f : 0.0f;   // cs -> sin(a)/2
    if (f != fp) return 0.0f;
    if (al == 0) return 0.5f;                       // cc,ss -> 1/2
    return f ? -0.5f : 0.5f;                        // cc -> +cos/2, ss -> -cos/2
}

__global__ void qsetup(const float* __restrict__ params,   // (3,4,3)
                       const float* __restrict__ W,        // (4,4)
                       const float* __restrict__ bvec)     // (4,)
{
    __shared__ float Ur[2][16][17];
    __shared__ float Ui[2][16][17];
    __shared__ float sG[12][8];
    __shared__ float sA[4][16][16];
    __shared__ float sS[4][4][4][9];
    __shared__ float sDt[4][9][9];

    const int t = threadIdx.x;
    const int n = t >> 4, c = t & 15;

    // --- phase A: 12 Rot gate matrices (fast trig) --------------------------
    if (t < 12) {
        float phi = params[t * 3 + 0];
        float th  = params[t * 3 + 1];
        float om  = params[t * 3 + 2];
        float ct, st, ca, sa, cb, sb;
        __sincosf(0.5f * th,         &st, &ct);
        __sincosf(0.5f * (phi + om), &sa, &ca);
        __sincosf(0.5f * (phi - om), &sb, &cb);
        sG[t][0] =  ca * ct;  sG[t][1] = -sa * ct;   // m00
        sG[t][2] = -cb * st;  sG[t][3] = -sb * st;   // m01
        sG[t][4] =  cb * st;  sG[t][5] = -sb * st;   // m10
        sG[t][6] =  ca * ct;  sG[t][7] =  sa * ct;   // m11
    }
    Ur[0][n][c] = (n == c) ? 1.0f : 0.0f;
    Ui[0][n][c] = 0.0f;
    __syncthreads();

    // --- phase B: gates + perms, double-buffered (1 barrier per step) ------
    int cur = 0;
    #pragma unroll
    for (int l = 0; l < 3; ++l) {
        #pragma unroll
        for (int w = 0; w < 4; ++w) {
            const int mask = 8 >> w;                 // wire 0 = MSB of row idx
            const float* g = sG[l * 4 + w];
            float xr = Ur[cur][n][c],        xi = Ui[cur][n][c];
            float yr = Ur[cur][n ^ mask][c], yi = Ui[cur][n ^ mask][c];
            float nr, ni;
            if (!(n & mask)) {
                nr = g[0]*xr - g[1]*xi + g[2]*yr - g[3]*yi;
                ni = g[0]*xi + g[1]*xr + g[2]*yi + g[3]*yr;
            } else {
                nr = g[4]*yr - g[5]*yi + g[6]*xr - g[7]*xi;
                ni = g[4]*yi + g[5]*yr + g[6]*xi + g[7]*xr;
            }
            Ur[cur ^ 1][n][c] = nr; Ui[cur ^ 1][n][c] = ni;
            __syncthreads();
            cur ^= 1;
        }
        // composed permutation of the layer's 4 sequential CNOTs
        const int r = (l % 3) + 1;
        int m = n;
        #pragma unroll
        for (int w = 3; w >= 0; --w) {
            const int cm = 8 >> w, tm = 8 >> ((w + r) & 3);
            if (m & cm) m ^= tm;
        }
        Ur[cur ^ 1][n][c] = Ur[cur][m][c];
        Ui[cur ^ 1][n][c] = Ui[cur][m][c];
        __syncthreads();
        cur ^= 1;
    }

    // --- phase C: A_k[i][j] = sum_w W[k][w] * Re(U^H Z_w U)[i][j] ----------
    {
        const int i = n, j = c;
        float M[4] = {0.f, 0.f, 0.f, 0.f};
        #pragma unroll
        for (int nn = 0; nn < 16; ++nn) {
            float v = Ur[cur][nn][i] * Ur[cur][nn][j]
                    + Ui[cur][nn][i] * Ui[cur][nn][j];
            #pragma unroll
            for (int w = 0; w < 4; ++w)
                M[w] += (nn & (8 >> w)) ? -v : v;
        }
        #pragma unroll
        for (int k = 0; k < 4; ++k) {
            float acc = 0.0f;
            #pragma unroll
            for (int w = 0; w < 4; ++w) acc += W[k * 4 + w] * M[w];
            sA[k][i][j] = acc;
        }
    }
    __syncthreads();

    // --- phase D stage 1: contract wires 2,3 ------------------------------
    for (int idx = t; idx < 576; idx += 256) {
        int k   = idx / 144;
        int rem = idx - k * 144;
        int i01 = rem / 36;
        int r2  = rem - i01 * 36;
        int j01 = r2 / 9;
        int v   = r2 - j01 * 9;
        int a2 = v / 3, a3 = v - a2 * 3;
        float acc = 0.0f;
        #pragma unroll
        for (int i23 = 0; i23 < 4; ++i23)
            #pragma unroll
            for (int j23 = 0; j23 < 4; ++j23) {
                float e = Ecoef(i23 >> 1, j23 >> 1, a2) * Ecoef(i23 & 1, j23 & 1, a3);
                acc += e * sA[k][i01 * 4 + i23][j01 * 4 + j23];
            }
        sS[k][i01][j01][v] = acc;
    }
    __syncthreads();

    // --- phase D stage 2: contract wires 0,1; fold bias --------------------
    for (int idx = t; idx < 324; idx += 256) {
        int k  = idx / 81;
        int uv = idx - k * 81;
        int u  = uv / 9;
        int v  = uv - u * 9;
        int a0 = u / 3, a1 = u - a0 * 3;
        float acc = 0.0f;
        #pragma unroll
        for (int i01 = 0; i01 < 4; ++i01)
            #pragma unroll
            for (int j01 = 0; j01 < 4; ++j01) {
                float e = Ecoef(i01 >> 1, j01 >> 1, a0) * Ecoef(i01 & 1, j01 & 1, a1);
                acc += e * sS[k][i01][j01][v];
            }
        if (u == 0 && v == 0) acc += bvec[k];
        sDt[k][u][v] = acc;
    }
    __syncthreads();

    // --- pack: slot t=(u*9+v) -> float4 (D0,D1,D2,D3) ----------------------
    // NOTE: v index order within each u must match the Horner grouping:
    // v = a2*3 + a3 with monomial {1,C2,S2}[a2] * {1,C3,S3}[a3].
    if (t < 81) {
        int u = t / 9, v = t - u * 9;
        reinterpret_cast<float4*>(g_D)[t] =
            make_float4(sDt[0][u][v], sDt[1][u][v], sDt[2][u][v], sDt[3][u][v]);
    }
}

__device__ __forceinline__ void patch_angles(const float* __restrict__ x, int gid,
                                             float* C, float* S)
{
    int b  = gid / 196;
    int p  = gid - b * 196;
    int pr = p / 14;
    int pc = p - pr * 14;
    const float* img = x + b * 784 + pr * 56 + pc * 2;
    float2 r0 = *reinterpret_cast<const float2*>(img);
    float2 r1 = *reinterpret_cast<const float2*>(img + 28);
    __sincosf(r0.x, &S[0], &C[0]);
    __sincosf(r0.y, &S[1], &C[1]);
    __sincosf(r1.x, &S[2], &C[2]);
    __sincosf(r1.y, &S[3], &C[3]);
}

__global__ void __launch_bounds__(256, 4) qmain(const float* __restrict__ x,
                                                float* __restrict__ out,
                                                int half, int total)
{
    int g0 = blockIdx.x * blockDim.x + threadIdx.x;
    if (g0 >= half) return;
    int g1 = g0 + half;
    bool has1 = (g1 < total);

    float Ca[4], Sa[4], Cb[4], Sb[4];           // [wire], patch A / patch B
    patch_angles(x, g0, Ca, Sa);
    patch_angles(x, has1 ? g1 : g0, Cb, Sb);

    // broadcast trig pairs per patch (wires 2,3)
    unsigned long long C2A, S2A, C3A, S3A, C2B, S2B, C3B, S3B;
    PACK_F32X2(C2A, Ca[2], Ca[2]);  PACK_F32X2(S2A, Sa[2], Sa[2]);
    PACK_F32X2(C3A, Ca[3], Ca[3]);  PACK_F32X2(S3A, Sa[3], Sa[3]);
    PACK_F32X2(C2B, Cb[2], Cb[2]);  PACK_F32X2(S2B, Sb[2], Sb[2]);
    PACK_F32X2(C3B, Cb[3], Cb[3]);  PACK_F32X2(S3B, Sb[3], Sb[3]);

    // accumulators: lanes = (out0,out1) / (out2,out3), per patch
    unsigned long long a01A, a23A, a01B, a23B;

    #pragma unroll
    for (int u = 0; u < 9; ++u) {
        // ---- q_u via Horner over m23 groups -------------------------------
        unsigned long long qxA, qyA, qxB, qyB, r;
        {
            ulonglong2 w0 = cD[u * 9 + 0];
            ulonglong2 w1 = cD[u * 9 + 1];
            ulonglong2 w2 = cD[u * 9 + 2];
            GROUP_EVAL(qxA, w0.x, w1.x, w2.x, C3A, S3A);
            GROUP_EVAL(qyA, w0.y, w1.y, w2.y, C3A, S3A);
            GROUP_EVAL(qxB, w0.x, w1.x, w2.x, C3B, S3B);
            GROUP_EVAL(qyB, w0.y, w1.y, w2.y, C3B, S3B);
        }
        {
            ulonglong2 w0 = cD[u * 9 + 3];
            ulonglong2 w1 = cD[u * 9 + 4];
            ulonglong2 w2 = cD[u * 9 + 5];
            GROUP_EVAL(r, w0.x, w1.x, w2.x, C3A, S3A);  FMA_F32X2(qxA, C2A, r, qxA);
            GROUP_EVAL(r, w0.y, w1.y, w2.y, C3A, S3A);  FMA_F32X2(qyA, C2A, r, qyA);
            GROUP_EVAL(r, w0.x, w1.x, w2.x, C3B, S3B);  FMA_F32X2(qxB, C2B, r, qxB);
            GROUP_EVAL(r, w0.y, w1.y, w2.y, C3B, S3B);  FMA_F32X2(qyB, C2B, r, qyB);
        }
        {
            ulonglong2 w0 = cD[u * 9 + 6];
            ulonglong2 w1 = cD[u * 9 + 7];
            ulonglong2 w2 = cD[u * 9 + 8];
            GROUP_EVAL(r, w0.x, w1.x, w2.x, C3A, S3A);  FMA_F32X2(qxA, S2A, r, qxA);
            GROUP_EVAL(r, w0.y, w1.y, w2.y, C3A, S3A);  FMA_F32X2(qyA, S2A, r, qyA);
            GROUP_EVAL(r, w0.x, w1.x, w2.x, C3B, S3B);  FMA_F32X2(qxB, S2B, r, qxB);
            GROUP_EVAL(r, w0.y, w1.y, w2.y, C3B, S3B);  FMA_F32X2(qyB, S2B, r, qyB);
        }

        // ---- accumulate m01[u] * q_u --------------------------------------
        if (u == 0) {
            a01A = qxA; a23A = qyA;
            a01B = qxB; a23B = qyB;
        } else {
            float mA = 1.0f, mB = 1.0f;
            if      (u == 1) { mA = Ca[1];        mB = Cb[1]; }
            else if (u == 2) { mA = Sa[1];        mB = Sb[1]; }
            else if (u == 3) { mA = Ca[0];        mB = Cb[0]; }
            else if (u == 4) { mA = Ca[0]*Ca[1];  mB = Cb[0]*Cb[1]; }
            else if (u == 5) { mA = Ca[0]*Sa[1];  mB = Cb[0]*Sb[1]; }
            else if (u == 6) { mA = Sa[0];        mB = Sb[0]; }
            else if (u == 7) { mA = Sa[0]*Ca[1];  mB = Sb[0]*Cb[1]; }
            else             { mA = Sa[0]*Sa[1];  mB = Sb[0]*Sb[1]; }
            unsigned long long mAp, mBp;
            PACK_F32X2(mAp, mA, mA);
            PACK_F32X2(mBp, mB, mB);
            FMA_F32X2(a01A, mAp, qxA, a01A);
            FMA_F32X2(a23A, mAp, qyA, a23A);
            FMA_F32X2(a01B, mBp, qxB, a01B);
            FMA_F32X2(a23B, mBp, qyB, a23B);
        }
    }

    float o0, o1, o2, o3;
    UNPACK_F32X2(o0, o1, a01A);
    UNPACK_F32X2(o2, o3, a23A);
    reinterpret_cast<float4*>(out)[g0] = make_float4(o0, o1, o2, o3);

    UNPACK_F32X2(o0, o1, a01B);
    UNPACK_F32X2(o2, o3, a23B);
    if (has1)
        reinterpret_cast<float4*>(out)[g1] = make_float4(o0, o1, o2, o3);
}

extern "C" void kernel_launch(void* const* d_in, const int* in_sizes, int n_in,
                              void* d_out, int out_size)
{
    const float* x      = (const float*)d_in[0];   // (B,1,28,28)
    const float* params = (const float*)d_in[1];   // (3,4,3)
    const float* W      = (const float*)d_in[2];   // (4,4)
    const float* bvec   = (const float*)d_in[3];   // (4,)
    float* out = (float*)d_out;                    // (B, 784)

    int total = in_sizes[0] / 4;                   // B*196 patches
    int half  = (total + 1) / 2;

    qsetup<<<1, 256>>>(params, W, bvec);

    // stage device-computed coefficients into constant memory (D2D, capturable)
    void* gptr = nullptr;
    cudaGetSymbolAddress(&gptr, g_D);
    cudaMemcpyToSymbolAsync(cD, gptr, sizeof(float) * 81 * 4, 0,
                            cudaMemcpyDeviceToDevice, 0);

    qmain<<<(half + 255) / 256, 256>>>(x, out, half, total);
}